// round 1
// baseline (speedup 1.0000x reference)
#include <cuda_runtime.h>
#include <math.h>

#define BLOCK 256
#define NMAX 2048
#define MAXH 1024

__global__ __launch_bounds__(BLOCK) void mkan_kernel(
    const float* __restrict__ x, const float* __restrict__ nodes,
    const float* __restrict__ w, const float* __restrict__ w1a,
    const float* __restrict__ w1b, const float* __restrict__ w2,
    float* __restrict__ out, int M, int N)
{
    __shared__ float s_nx[NMAX], s_ny[NMAX], s_w[NMAX];
    __shared__ float s_kw[120];          // w1a[40] | w1b[40] | w2[40]
    __shared__ float s_dist[NMAX];       // orphan path only
    __shared__ int   s_hits[MAXH];
    __shared__ int   s_nhits;
    __shared__ float s_red[2][BLOCK / 32];
    __shared__ float s_sums[2];
    __shared__ unsigned long long s_key;
    __shared__ float s_seld[8];
    __shared__ int   s_seli[8];

    const int tid = threadIdx.x;

    // Stage nodes + w + KAN weights into shared once per block.
    for (int i = tid; i < N; i += BLOCK) {
        float2 nd = ((const float2*)nodes)[i];
        s_nx[i] = nd.x;
        s_ny[i] = nd.y;
        s_w[i]  = w[i];
    }
    if (tid < 120) {
        s_kw[tid] = (tid < 40) ? w1a[tid] : (tid < 80) ? w1b[tid - 40] : w2[tid - 80];
    }
    __syncthreads();

    const float radius = 0.06f;
    const float inv_r  = 1.0f / 0.06f;
    const float r2     = radius * radius;
    const float inv_h  = 1.0f / 0.75f;

    for (int m = blockIdx.x; m < M; m += gridDim.x) {
        const float px = x[2 * m];
        const float py = x[2 * m + 1];

        if (tid == 0) s_nhits = 0;
        __syncthreads();

        // ---- Phase A: dense distance pass, compact in-radius indices ----
        for (int n = tid; n < N; n += BLOCK) {
            float dx = px - s_nx[n];
            float dy = py - s_ny[n];
            float d2 = dx * dx + dy * dy;
            if (d2 <= r2) {
                int slot = atomicAdd(&s_nhits, 1);
                if (slot < MAXH) s_hits[slot] = n;
            }
        }
        __syncthreads();
        const int nh = min(s_nhits, MAXH);

        // ---- Phase B: KAN + window on compacted hits ----
        float lsum = 0.0f, lws = 0.0f;
        for (int i = tid; i < nh; i += BLOCK) {
            const int n = s_hits[i];
            float dx = px - s_nx[n];
            float dy = py - s_ny[n];
            float d2 = dx * dx + dy * dy;
            float dist = sqrtf(d2);
            float u = dx * inv_r;
            float v = dy * inv_r;

            float b0[5], b1[5];
            #pragma unroll
            for (int k = 0; k < 5; k++) {
                float g = -1.5f + 0.75f * (float)k;
                b0[k] = fmaxf(0.0f, 1.0f - fabsf(u - g) * inv_h);
                b1[k] = fmaxf(0.0f, 1.0f - fabsf(v - g) * inv_h);
            }
            float acc = 0.0f;
            #pragma unroll
            for (int j = 0; j < 8; j++) {
                float hd = 0.0f;
                #pragma unroll
                for (int k = 0; k < 5; k++)
                    hd += b0[k] * s_kw[j * 5 + k] + b1[k] * s_kw[40 + j * 5 + k];
                #pragma unroll
                for (int k = 0; k < 5; k++) {
                    float g = -1.5f + 0.75f * (float)k;
                    acc += fmaxf(0.0f, 1.0f - fabsf(hd - g) * inv_h) * s_kw[80 + j * 5 + k];
                }
            }
            float sp = (acc > 20.0f) ? acc : log1pf(expf(acc));

            float q = dist * inv_r;   // q <= 1 guaranteed by gate
            float win;
            if (q <= 0.5f)
                win = 2.0f / 3.0f + q * q * (4.0f * q - 4.0f);
            else
                win = 4.0f / 3.0f + q * (-4.0f + q * (4.0f - (4.0f / 3.0f) * q));

            float phi = sp * win;
            lsum += phi;
            lws  += phi * s_w[n];
        }

        // ---- Phase C: block reduction of (phi_sum, phi*w sum) ----
        #pragma unroll
        for (int off = 16; off > 0; off >>= 1) {
            lsum += __shfl_down_sync(0xffffffffu, lsum, off);
            lws  += __shfl_down_sync(0xffffffffu, lws,  off);
        }
        const int wid = tid >> 5, lane = tid & 31;
        if (lane == 0) { s_red[0][wid] = lsum; s_red[1][wid] = lws; }
        __syncthreads();
        if (tid == 0) {
            float a = 0.0f, b = 0.0f;
            #pragma unroll
            for (int i = 0; i < BLOCK / 32; i++) { a += s_red[0][i]; b += s_red[1][i]; }
            s_sums[0] = a;
            s_sums[1] = b;
        }
        __syncthreads();
        const float phi_sum = s_sums[0];
        const float phiw_sum = s_sums[1];

        if (phi_sum >= 1e-14f) {
            if (tid == 0) out[m] = phiw_sum / (phi_sum + 1e-12f);
            __syncthreads();
        } else {
            // ---- Orphan: exact kNN (k=8) fallback ----
            for (int n = tid; n < N; n += BLOCK) {
                float dx = px - s_nx[n];
                float dy = py - s_ny[n];
                s_dist[n] = sqrtf(dx * dx + dy * dy);
            }
            __syncthreads();
            const int kk = (N < 8) ? N : 8;
            for (int r = 0; r < kk; r++) {
                if (tid == 0) s_key = 0xffffffffffffffffull;
                __syncthreads();
                unsigned long long local = 0xffffffffffffffffull;
                for (int n = tid; n < N; n += BLOCK) {
                    unsigned long long key =
                        (((unsigned long long)__float_as_uint(s_dist[n])) << 32) |
                        (unsigned long long)(unsigned)n;
                    local = (key < local) ? key : local;
                }
                // warp-level min first, then one atomic per warp
                #pragma unroll
                for (int off = 16; off > 0; off >>= 1) {
                    unsigned long long o = __shfl_down_sync(0xffffffffu, local, off);
                    local = (o < local) ? o : local;
                }
                if (lane == 0) atomicMin(&s_key, local);
                __syncthreads();
                if (tid == 0) {
                    unsigned long long k = s_key;
                    int idx = (int)(k & 0xffffffffull);
                    s_seld[r] = __uint_as_float((unsigned)(k >> 32));
                    s_seli[r] = idx;
                    s_dist[idx] = __int_as_float(0x7f800000);  // +inf, exclude
                }
                __syncthreads();
            }
            if (tid == 0) {
                const float alpha = 20.0f / 0.06f;
                float wsum = 0.0f, accw = 0.0f;
                for (int r = 0; r < kk; r++) {
                    float e = expf(-alpha * s_seld[r]);
                    wsum += e;
                    accw += e * s_w[s_seli[r]];
                }
                out[m] = accw / (wsum + 1e-18f);
            }
            __syncthreads();
        }
    }
}

extern "C" void kernel_launch(void* const* d_in, const int* in_sizes, int n_in,
                              void* d_out, int out_size) {
    const float* x     = (const float*)d_in[0];
    const float* nodes = (const float*)d_in[1];
    const float* w     = (const float*)d_in[2];
    const float* w1a   = (const float*)d_in[3];
    const float* w1b   = (const float*)d_in[4];
    const float* w2    = (const float*)d_in[5];
    float* out = (float*)d_out;

    int M = in_sizes[0] / 2;
    int N = in_sizes[1] / 2;

    int grid = (M < 512) ? M : 512;
    mkan_kernel<<<grid, BLOCK>>>(x, nodes, w, w1a, w1b, w2, out, M, N);
}

// round 2
// speedup vs baseline: 1.5792x; 1.5792x over previous
#include <cuda_runtime.h>
#include <math.h>

#define WPB   4                 // warps (rows) per block
#define BLOCK (WPB * 32)
#define HBUF  256               // per-warp hit buffer (expected ~23 hits)

__device__ __forceinline__ float kan_softplus(float u, float v, const float* __restrict__ s_kw) {
    const float inv_h = 1.0f / 0.75f;
    float b0[5], b1[5];
    #pragma unroll
    for (int k = 0; k < 5; k++) {
        float g = -1.5f + 0.75f * (float)k;
        b0[k] = fmaxf(0.0f, 1.0f - fabsf(u - g) * inv_h);
        b1[k] = fmaxf(0.0f, 1.0f - fabsf(v - g) * inv_h);
    }
    float acc = 0.0f;
    #pragma unroll
    for (int j = 0; j < 8; j++) {
        float hd = 0.0f;
        #pragma unroll
        for (int k = 0; k < 5; k++)
            hd += b0[k] * s_kw[j * 5 + k] + b1[k] * s_kw[40 + j * 5 + k];
        #pragma unroll
        for (int k = 0; k < 5; k++) {
            float g = -1.5f + 0.75f * (float)k;
            acc += fmaxf(0.0f, 1.0f - fabsf(hd - g) * inv_h) * s_kw[80 + j * 5 + k];
        }
    }
    return (acc > 20.0f) ? acc : log1pf(expf(acc));
}

__device__ __forceinline__ float cubic_window(float q) {
    // q <= 1 guaranteed by caller's gate
    if (q <= 0.5f)
        return 2.0f / 3.0f + q * q * (4.0f * q - 4.0f);
    return 4.0f / 3.0f + q * (-4.0f + q * (4.0f - (4.0f / 3.0f) * q));
}

__global__ __launch_bounds__(BLOCK) void mkan_kernel(
    const float* __restrict__ x, const float* __restrict__ nodes,
    const float* __restrict__ w, const float* __restrict__ w1a,
    const float* __restrict__ w1b, const float* __restrict__ w2,
    float* __restrict__ out, int M, int N)
{
    __shared__ float s_kw[120];                  // w1a[40] | w1b[40] | w2[40]
    __shared__ int   s_hits[WPB][HBUF];

    const int tid  = threadIdx.x;
    const int wid  = tid >> 5;
    const int lane = tid & 31;

    if (tid < 120)
        s_kw[tid] = (tid < 40) ? w1a[tid] : (tid < 80) ? w1b[tid - 40] : w2[tid - 80];
    __syncthreads();

    const int m = blockIdx.x * WPB + wid;
    if (m >= M) return;

    const float2 p = __ldg(&((const float2*)x)[m]);
    const float  px = p.x, py = p.y;

    const float radius = 0.06f;
    const float inv_r  = 1.0f / 0.06f;
    const float r2     = radius * radius;
    const float2* __restrict__ nd2 = (const float2*)nodes;

    // ---- Phase A: distance pass with warp ballot-compaction ----
    int cnt = 0;
    for (int base = 0; base < N; base += 32) {
        const int n = base + lane;
        bool hit = false;
        if (n < N) {
            float2 nd = __ldg(&nd2[n]);
            float dx = px - nd.x;
            float dy = py - nd.y;
            float d2 = fmaf(dx, dx, dy * dy);
            hit = (d2 <= r2);
        }
        unsigned mask = __ballot_sync(0xffffffffu, hit);
        if (hit) {
            int pos = cnt + __popc(mask & ((1u << lane) - 1u));
            if (pos < HBUF) s_hits[wid][pos] = n;
        }
        cnt += __popc(mask);
    }
    __syncwarp();

    // ---- Phase B: KAN + window on compacted hits ----
    float lsum = 0.0f, lws = 0.0f;
    if (cnt <= HBUF) {
        for (int i = lane; i < cnt; i += 32) {
            const int n = s_hits[wid][i];
            float2 nd = __ldg(&nd2[n]);
            float dx = px - nd.x;
            float dy = py - nd.y;
            float d2 = fmaf(dx, dx, dy * dy);
            float sp = kan_softplus(dx * inv_r, dy * inv_r, s_kw);
            float phi = sp * cubic_window(sqrtf(d2) * inv_r);
            lsum += phi;
            lws  += phi * __ldg(&w[n]);
        }
    } else {
        // overflow fallback (statistically never taken): dense divergent pass
        for (int n = lane; n < N; n += 32) {
            float2 nd = __ldg(&nd2[n]);
            float dx = px - nd.x;
            float dy = py - nd.y;
            float d2 = fmaf(dx, dx, dy * dy);
            if (d2 <= r2) {
                float sp = kan_softplus(dx * inv_r, dy * inv_r, s_kw);
                float phi = sp * cubic_window(sqrtf(d2) * inv_r);
                lsum += phi;
                lws  += phi * __ldg(&w[n]);
            }
        }
    }

    // ---- Phase C: warp butterfly reduction (all lanes end with totals) ----
    #pragma unroll
    for (int off = 16; off > 0; off >>= 1) {
        lsum += __shfl_xor_sync(0xffffffffu, lsum, off);
        lws  += __shfl_xor_sync(0xffffffffu, lws,  off);
    }

    if (lsum >= 1e-14f) {
        if (lane == 0) out[m] = lws / (lsum + 1e-12f);
        return;
    }

    // ---- Orphan: exact warp-local kNN (k=8) fallback ----
    const int kk = (N < 8) ? N : 8;
    unsigned long long last = 0ull;
    float seld = 0.0f;
    int   seli = 0;
    for (int r = 0; r < kk; r++) {
        unsigned long long best = 0xffffffffffffffffull;
        for (int n = lane; n < N; n += 32) {
            float2 nd = __ldg(&nd2[n]);
            float dx = px - nd.x;
            float dy = py - nd.y;
            float dist = sqrtf(fmaf(dx, dx, dy * dy));
            unsigned long long key =
                (((unsigned long long)__float_as_uint(dist)) << 32) |
                (unsigned long long)(unsigned)n;
            if ((r == 0 || key > last) && key < best) best = key;
        }
        #pragma unroll
        for (int off = 16; off > 0; off >>= 1) {
            unsigned long long o = __shfl_xor_sync(0xffffffffu, best, off);
            best = (o < best) ? o : best;
        }
        last = best;
        if (lane == r) {
            seld = __uint_as_float((unsigned)(best >> 32));
            seli = (int)(best & 0xffffffffull);
        }
    }
    float e = 0.0f, ew = 0.0f;
    if (lane < kk) {
        e  = expf(-(20.0f / 0.06f) * seld);
        ew = e * __ldg(&w[seli]);
    }
    #pragma unroll
    for (int off = 16; off > 0; off >>= 1) {
        e  += __shfl_xor_sync(0xffffffffu, e,  off);
        ew += __shfl_xor_sync(0xffffffffu, ew, off);
    }
    if (lane == 0) out[m] = ew / (e + 1e-18f);
}

extern "C" void kernel_launch(void* const* d_in, const int* in_sizes, int n_in,
                              void* d_out, int out_size) {
    const float* x     = (const float*)d_in[0];
    const float* nodes = (const float*)d_in[1];
    const float* w     = (const float*)d_in[2];
    const float* w1a   = (const float*)d_in[3];
    const float* w1b   = (const float*)d_in[4];
    const float* w2    = (const float*)d_in[5];
    float* out = (float*)d_out;

    int M = in_sizes[0] / 2;
    int N = in_sizes[1] / 2;

    int grid = (M + WPB - 1) / WPB;
    mkan_kernel<<<grid, BLOCK>>>(x, nodes, w, w1a, w1b, w2, out, M, N);
}